// round 12
// baseline (speedup 1.0000x reference)
#include <cuda_runtime.h>
#include <cuda_bf16.h>
#include <cstdint>

#define W 256
#define BH 64
#define NBLOCKS 512           // 128 images * 4 bands
#define MAGF 516              // floats per mag slot (258 float2)

__device__ float g_partials[NBLOCKS];
__device__ unsigned int g_ticket;   // zero-init; atomicInc wraps after NBLOCKS -> graph-replay safe

// Gaussian taps, computed as numpy does (f64 exp, f64 normalize, cast f32)
constexpr double E2d  = 0.1353352832366127;   // exp(-2)
constexpr double E05d = 0.6065306597126334;   // exp(-0.5)
constexpr double GSUM = 1.0 + 2.0 * (E2d + E05d);
constexpr float  G0 = (float)(E2d / GSUM);
constexpr float  G1 = (float)(E05d / GSUM);
constexpr float  G2 = (float)(1.0 / GSUM);

// Quadrant-exact tangent thresholds for k = 4 + round(atan2(gy,gx)*4/3.14159)
#define TLO_POS 0.414213174f
#define THI_POS 2.414206767f
#define TLO_NEG 0.414216283f
#define THI_NEG 2.414224887f

__device__ __forceinline__ int dir_idx(float gx, float gy) {
    float ax = fabsf(gx), ay = fabsf(gy);
    bool xn = gx < 0.0f;
    float tlo = xn ? TLO_NEG : TLO_POS;
    float thi = xn ? THI_NEG : THI_POS;
    int s = (ay >= ax * tlo) ? ((ay > ax * thi) ? 2 : 1) : 0;
    int kp = xn ? (4 - s) : s;
    int k = (gy < 0.0f) ? (4 - kp) : (4 + kp);
    return k & 7;
}

// NMS neighbor offsets packed in nibbles: (dr+1),(dc+1) per idx (validated rel_err=0)
#define DRP 0x00012221u
#define DCP 0x21000122u

// Operates on SQUARED magnitudes. sqrtf only on pass (rare). em4 = er&3 (compile-time).
__device__ __forceinline__ float nms_one(float msq, int idx, const float* base, int em4) {
    int dr = (int)((DRP >> (idx * 4)) & 3u) - 1;
    int dc = (int)((DCP >> (idx * 4)) & 3u) - 1;
    float np = base[((em4 + dr) & 3) * MAGF + 2 * dc];
    float nn = base[((em4 - dr) & 3) * MAGF - 2 * dc];
    bool pass = (fminf(msq - np, msq - nn) > 0.0f) && (msq >= 4.0f);
    return pass ? sqrtf(msq) : 0.0f;
}

// float2 layout everywhere: .x = image0, .y = image1
__global__ __launch_bounds__(256, 4) void canny_fused(const float* __restrict__ in0,
                                                      const float* __restrict__ in1,
                                                      float* __restrict__ out) {
    const int t   = threadIdx.x;            // column
    const int blk = blockIdx.x;
    const int n   = blk >> 2;               // image
    const int r0  = (blk & 3) * BH;         // band start row (multiple of 64)
    const float* b0 = in0 + n * (W * W) + t;
    const float* b1 = in1 + n * (W * W) + t;

    __shared__ __align__(8) float2 sh_prep[4][W + 4];   // 4-slot ring; col c -> idx c+2
    __shared__ __align__(8) float2 sh_bl[2][W + 2];     // col c -> idx c+1
    __shared__ __align__(8) float2 sh_mag[4][W + 2];    // SQUARED mags; col c -> idx c+1
    __shared__ float  red[256];
    __shared__ double sdd[256];
    __shared__ unsigned s_last;

    // zero everything once (guards stay zero; data cells get overwritten)
    {
        float2 z = make_float2(0.f, 0.f);
        float2* zp = (float2*)sh_prep;
        for (int i = t; i < 4 * (W + 4); i += 256) zp[i] = z;
        float2* zb = (float2*)sh_bl;
        for (int i = t; i < 2 * (W + 2); i += 256) zb[i] = z;
        float2* zm = (float2*)sh_mag;
        for (int i = t; i < 4 * (W + 2); i += 256) zm[i] = z;
    }

    // register rings
    float2 hb0, hb1, hb2, hb3, hb4;                  // hblur rows ir-6..ir-2 (post-push)
    hb0 = hb1 = hb2 = hb3 = hb4 = make_float2(0.f, 0.f);
    // named A/B slots, indexed by (row & 3) at compile time (no ring shifts)
    float2 Ar0, Ar1, Ar2, Ar3, Br0, Br1, Br2, Br3;
    Ar0 = Ar1 = Ar2 = Ar3 = Br0 = Br1 = Br2 = Br3 = make_float2(0.f, 0.f);
    float2 v_prev = make_float2(0.f, 0.f);           // vblur of row ir-5 (A/B center tap)
    int d1i = 0, d2i = 0;                            // dirs (bits 0-7) + pass flag (bit 16)
    float acc = 0.f;

    const float* mbase0 = &sh_mag[0][t + 1].x;
    const float* mbase1 = &sh_mag[0][t + 1].y;

    // software prefetch of the current row, one iteration ahead
    float qa0 = 0.f, qa1 = 0.f;
    {
        const int irf = r0 - 4;
        if ((unsigned)irf < (unsigned)W) { qa0 = b0[irf * W]; qa1 = b1[irf * W]; }
    }

    __syncthreads();

    // 76 iterations: ir = r0-4 .. r0+BH+7.  r0 % 4 == 0  ->  ir ≡ j (mod 4).
    // PRE-barrier : prefetch ir+1 | LDS prep(ir-2) | hblur ir-2 | vblur ir-4
    // POST-barrier: STS prep ir | STS bl ir-4 | A/B ir-5 | magsq ir-6 | NMS ir-8
    #pragma unroll 1
    for (int ir0 = r0 - 4; ir0 < r0 + BH + 8; ir0 += 4) {
        #pragma unroll
        for (int j = 0; j < 4; ++j) {
            const int ir = ir0 + j;

            // ---- prefetch row ir+1 (consumed next iteration) ----
            float qb0 = 0.f, qb1 = 0.f;
            {
                const int irn = ir + 1;
                if ((unsigned)irn < (unsigned)W) { qb0 = b0[irn * W]; qb1 = b1[irn * W]; }
            }

            // ---- hblur row ir-2 (slot written 2 iters ago; barrier in between) ----
            float2 h;
            {
                const float2* pr = sh_prep[(j + 2) & 3];
                float2 a0 = pr[t], a1 = pr[t + 1], a2 = pr[t + 2], a3 = pr[t + 3], a4 = pr[t + 4];
                h.x = G0 * (a0.x + a4.x) + G1 * (a1.x + a3.x) + G2 * a2.x;
                h.y = G0 * (a0.y + a4.y) + G1 * (a1.y + a3.y) + G2 * a2.y;
            }
            hb0 = hb1; hb1 = hb2; hb2 = hb3; hb3 = hb4; hb4 = h;

            // ---- vblur row ir-4 (pure registers) ----
            float2 v = make_float2(0.f, 0.f);
            {
                const int br = ir - 4;
                if ((unsigned)br < (unsigned)W) {
                    v.x = G0 * (hb0.x + hb4.x) + G1 * (hb1.x + hb3.x) + G2 * hb2.x;
                    v.y = G0 * (hb0.y + hb4.y) + G1 * (hb1.y + hb3.y) + G2 * hb2.y;
                }
            }

            __syncthreads();   // single barrier

            // ---- prep row ir (transform inside guard: OOB rows contribute exact 0) ----
            {
                float2 p = make_float2(0.f, 0.f);
                if ((unsigned)ir < (unsigned)W)
                    p = make_float2((qa0 + 1.0f) * 0.5f, (qa1 + 1.0f) * 0.5f);
                sh_prep[j][t + 2] = p;
            }

            // ---- store vblur row ir-4 ----
            sh_bl[j & 1][t + 1] = v;

            // ---- A/B aggregates row ir-5 (bl written last iter; center from v_prev) ----
            {
                const float2* bl = sh_bl[(j + 1) & 1];
                float2 l = bl[t], r = bl[t + 2];
                float2 c = v_prev;
                float2& Aw = ((j + 3) & 3) == 0 ? Ar0 : ((j + 3) & 3) == 1 ? Ar1
                           : ((j + 3) & 3) == 2 ? Ar2 : Ar3;
                float2& Bw = ((j + 3) & 3) == 0 ? Br0 : ((j + 3) & 3) == 1 ? Br1
                           : ((j + 3) & 3) == 2 ? Br2 : Br3;
                Aw.x = l.x + 2.0f * c.x + r.x;   Bw.x = l.x - r.x;
                Aw.y = l.y + 2.0f * c.y + r.y;   Bw.y = l.y - r.y;
            }
            v_prev = v;

            // ---- Sobel + SQUARED magnitude row ir-6; dirs+flag packed under skip ----
            float2 nm = make_float2(0.f, 0.f);
            int ni = 0;
            {
                const int mr = ir - 6;
                if ((unsigned)mr < (unsigned)W) {
                    const float2& Am = ((j + 1) & 3) == 0 ? Ar0 : ((j + 1) & 3) == 1 ? Ar1
                                     : ((j + 1) & 3) == 2 ? Ar2 : Ar3;   // row mr-1
                    const float2& Ap = ((j + 3) & 3) == 0 ? Ar0 : ((j + 3) & 3) == 1 ? Ar1
                                     : ((j + 3) & 3) == 2 ? Ar2 : Ar3;   // row mr+1
                    const float2& Bm = ((j + 1) & 3) == 0 ? Br0 : ((j + 1) & 3) == 1 ? Br1
                                     : ((j + 1) & 3) == 2 ? Br2 : Br3;   // row mr-1
                    const float2& Bc = ((j + 2) & 3) == 0 ? Br0 : ((j + 2) & 3) == 1 ? Br1
                                     : ((j + 2) & 3) == 2 ? Br2 : Br3;   // row mr
                    const float2& Bp = ((j + 3) & 3) == 0 ? Br0 : ((j + 3) & 3) == 1 ? Br1
                                     : ((j + 3) & 3) == 2 ? Br2 : Br3;   // row mr+1
                    float gx0 = Bm.x + 2.0f * Bc.x + Bp.x;
                    float gy0 = Am.x - Ap.x;
                    nm.x = gx0 * gx0 + gy0 * gy0;
                    float gx1 = Bm.y + 2.0f * Bc.y + Bp.y;
                    float gy1 = Am.y - Ap.y;
                    nm.y = gx1 * gx1 + gy1 * gy1;
                    if (__any_sync(0xffffffffu, fmaxf(nm.x, nm.y) >= 4.0f))
                        ni = dir_idx(gx0, gy0) | (dir_idx(gx1, gy1) << 4) | 0x10000;
                }
                sh_mag[(j + 2) & 3][t + 1] = nm;
            }

            // ---- NMS row er = ir-8 (mag slot = j); flag is warp-uniform ----
            {
                const int er = ir - 8;
                if ((unsigned)(er - r0) < (unsigned)BH && (d2i & 0x10000)) {
                    float2 cm = sh_mag[j][t + 1];   // own center mag^2 (written 2 iters ago)
                    float e0 = nms_one(cm.x, d2i & 7,        mbase0, j);
                    float e1 = nms_one(cm.y, (d2i >> 4) & 7, mbase1, j);
                    acc += fabsf(e0 - e1);
                }
            }

            d2i = d1i; d1i = ni;
            qa0 = qb0; qa1 = qb1;
        }
    }

    // deterministic block reduction
    red[t] = acc;
    __syncthreads();
    #pragma unroll
    for (int off = 128; off > 0; off >>= 1) {
        if (t < off) red[t] += red[t + off];
        __syncthreads();
    }

    if (t == 0) {
        g_partials[blk] = red[0];
        __threadfence();
        unsigned old = atomicInc(&g_ticket, NBLOCKS - 1);   // wraps to 0 -> replay-safe
        s_last = (old == NBLOCKS - 1) ? 1u : 0u;
    }
    __syncthreads();

    // last block deterministically reduces all partials (double precision)
    if (s_last) {
        double s = 0.0;
        for (int i = t; i < NBLOCKS; i += 256) s += (double)__ldcg(&g_partials[i]);
        sdd[t] = s;
        __syncthreads();
        #pragma unroll
        for (int off = 128; off > 0; off >>= 1) {
            if (t < off) sdd[t] += sdd[t + off];
            __syncthreads();
        }
        if (t == 0) out[0] = (float)(sdd[0] / 8388608.0);
    }
}

extern "C" void kernel_launch(void* const* d_in, const int* in_sizes, int n_in,
                              void* d_out, int out_size) {
    const float* gt = (const float*)d_in[0];   // data_input
    const float* pr = (const float*)d_in[1];   // model_output
    canny_fused<<<NBLOCKS, 256>>>(gt, pr, (float*)d_out);
}